// round 15
// baseline (speedup 1.0000x reference)
#include <cuda_runtime.h>

#define W 512
#define H 512
#define NPLANES 96
#define SKEW 2               // minimal skew: lane l -> col c = t - 2l
#define NWARPS 16            // one band (32 rows) per warp, whole plane per block
#define CH 16                // columns per sync chunk
#define LAG 64               // 32 rows * SKEW: producer lead needed by consumer
#define NSTEP_PAD 576        // 512 + 2*31 = 574, padded to 36 chunks of 16
#define NCHUNK (NSTEP_PAD / CH)

// Floyd-Steinberg 1-bit error diffusion.
// Byte-identical to the 229us skew-2 kernel except for ONE semantic change:
// REVERSED band mapping (warp w -> band 15-w). The B300 warp arbiter is
// hi-wid-first; with band==w the spinning (not-yet-started, high-band) warps
// are the HIGH-wid warps and win issue arbitration over the active warps'
// dependency-chain instructions on every conflict. Reversed, waiting bands sit
// on low-wid warps (lowest priority), the cascade leader holds top priority,
// and finished warps exit. Dataflow is unchanged — pure warp permutation.
__global__ void __launch_bounds__(NWARPS * 32, 1)
fs_dither_kernel(const float* __restrict__ x, float* __restrict__ out) {
    __shared__ float errbuf[NWARPS][W];
    __shared__ float zbuf[W];
    __shared__ volatile unsigned progress[NWARPS];

    const int tid = threadIdx.x;
    const int w = tid >> 5;
    const int lane = tid & 31;
    const int plane = blockIdx.x;

    const int band = (NWARPS - 1) - w;   // reversed mapping (see header)

    const float* __restrict__ xp = x + (size_t)plane * (H * W);
    float* __restrict__ op = out + (size_t)plane * (H * W);

    for (int i = tid; i < W; i += NWARPS * 32) zbuf[i] = 0.0f;
    if (tid < NWARPS) progress[tid] = 0u;
    __syncthreads();

    const float* __restrict__ prevrow = (band == 0) ? zbuf : errbuf[band - 1];
    float* __restrict__ myrow = errbuf[band];

    const int row = band * 32 + lane;
    const float* __restrict__ xrow = xp + (size_t)row * W;
    float* __restrict__ orow = op + (size_t)row * W;

    // Skew-2 delay line: at step t lane l consumes
    //   e_ur = r1 (row-above err at col c+1, shfl'd at end of step t-1)
    //   e_u  = r2 (col c,   shfl'd at t-2)
    //   e_ul = r3 (col c-1, shfl'd at t-3)
    // Lane 0 substitutes prevrow[t+2] into the shfl each step.
    float r1 = 0.0f, r2 = 0.0f, r3 = 0.0f;
    float left = 0.0f;

    int t = 0;
    for (int k = 0; k < NCHUNK; ++k) {
        if (band != 0) {
            unsigned need = (unsigned)(t + CH + LAG);
            if (need > NSTEP_PAD) need = NSTEP_PAD;
            while (progress[band - 1] < need) { /* spin */ }
        }
        __syncwarp();
        __threadfence_block();   // acquire: producer's STS now visible

        if (k == 0 && lane == 0) {
            // e_ul(t=0) = prev[-1] = 0 (pad); e_u = prev[0]; e_ur = prev[1].
            r3 = 0.0f;
            r2 = prevrow[0];
            r1 = prevrow[1];
        }

        #pragma unroll
        for (int i = 0; i < CH; ++i, ++t) {
            const int c = t - SKEW * lane;
            const bool active = ((unsigned)c < (unsigned)W);
            const float e_ur = r1, e_u = r2, e_ul = r3;

            // Clamped-address load keeps inactive lanes branch-free (L1-hit).
            int cl = c < 0 ? 0 : (c > W - 1 ? W - 1 : c);
            float xv = __ldg(xrow + cl);

            // x = clip(x,-1,1); x01 = (x+1)/2  (exact, matches reference)
            xv = fminf(fmaxf(xv, -1.0f), 1.0f);
            float x01 = __fmul_rn(__fadd_rn(xv, 1.0f), 0.5f);

            // up = (1/16*e_ul + 5/16*e_u) + 3/16*e_ur  (reference order, no FMA)
            float u = __fadd_rn(__fadd_rn(__fmul_rn(0.0625f, e_ul),
                                          __fmul_rn(0.3125f, e_u)),
                                __fmul_rn(0.1875f, e_ur));
            float pre = __fadd_rn(x01, u);
            float raw = __fadd_rn(pre, __fmul_rn(0.4375f, left));
            float val = fminf(fmaxf(raw, 0.0f), 1.0f);

            // q = round-half-even(val), val in [0,1]  <=>  raw > 0.5.
            // d = 0.5 - raw has exact sign (Sterbenz in [0.25,1]); tie -> q=0.
            float d = __fadd_rn(0.5f, -raw);
            unsigned s = (unsigned)(__float_as_int(d) >> 31);
            // err = val - q exactly: val + (-1.0f masked); Sterbenz-exact.
            float err = __fadd_rn(val, __uint_as_float(s & 0xBF800000u));
            err = active ? err : 0.0f;   // inactive lanes feed zero padding

            if (active) {
                // output = 2*q - 1 in {-1,+1}
                orow[c] = __uint_as_float(0xBF800000u ^ (s & 0x80000000u));
                if (lane == 31) myrow[c] = err;   // hand off to next band
            }
            left = err;

            // Cross-lane propagation; lane 0 injects the prev band's err.
            float sh = __shfl_up_sync(0xFFFFFFFFu, err, 1);
            const int pi = t + SKEW;
            float pv = (pi < W) ? prevrow[pi] : 0.0f;  // broadcast LDS
            if (lane == 0) sh = pv;                    // SEL, no branch
            r3 = r2; r2 = r1; r1 = sh;
        }

        if (lane == 31) {
            __threadfence_block();        // release: STS before counter
            progress[band] = (unsigned)t;
        }
    }
}

extern "C" void kernel_launch(void* const* d_in, const int* in_sizes, int n_in,
                              void* d_out, int out_size) {
    (void)in_sizes; (void)n_in; (void)out_size;
    const float* x = (const float*)d_in[0];
    float* out = (float*)d_out;
    fs_dither_kernel<<<NPLANES, NWARPS * 32>>>(x, out);
}

// round 16
// speedup vs baseline: 1.0173x; 1.0173x over previous
#include <cuda_runtime.h>

#define W 512
#define H 512
#define NPLANES 96
#define SKEW 2               // minimal skew: lane l -> col c = t - 2l
#define NWARPS 16            // one band (32 rows) per warp, whole plane per block
#define CH 16                // columns per sync chunk
#define LAG 64               // 32 rows * SKEW: producer lead needed by consumer
#define NSTEP_PAD 576        // 512 + 2*31 = 574, padded to 36 chunks of 16
#define NCHUNK (NSTEP_PAD / CH)

// Compiler-only memory barrier: stops reordering/hoisting across the handoff
// without emitting a MEMBAR instruction.
#define COMPILER_FENCE() asm volatile("" ::: "memory")

// Floyd-Steinberg 1-bit error diffusion.
// Byte-identical to the 229us skew-2 kernel except ONE change: the two
// __threadfence_block() calls per chunk are now compiler-only fences.
// Rationale: MEMBAR.ALL.CTA costs 36 + k(nw)*n_STS_in_flight; with 16 warps
// each carrying ~16 in-flight STG/STS per chunk, the two fences plausibly
// dominate the ~3700-cyc steady-state chunk period (the 16-step chain needs
// only ~1000). HW ordering is preserved without MEMBAR: per-warp SMEM ops
// commit through the in-order LSU queue, so the producer's myrow STS precedes
// its volatile progress STS, and the consumer's prevrow LDS are control-
// dependent on the volatile poll (no memory speculation). The compiler fence
// prevents compiler-level hoisting. Bit-exact rel_err==0 is the watchdog.
__global__ void __launch_bounds__(NWARPS * 32, 1)
fs_dither_kernel(const float* __restrict__ x, float* __restrict__ out) {
    __shared__ float errbuf[NWARPS][W];
    __shared__ float zbuf[W];
    __shared__ volatile unsigned progress[NWARPS];

    const int tid = threadIdx.x;
    const int w = tid >> 5;
    const int lane = tid & 31;
    const int plane = blockIdx.x;

    const float* __restrict__ xp = x + (size_t)plane * (H * W);
    float* __restrict__ op = out + (size_t)plane * (H * W);

    for (int i = tid; i < W; i += NWARPS * 32) zbuf[i] = 0.0f;
    if (tid < NWARPS) progress[tid] = 0u;
    __syncthreads();

    const float* __restrict__ prevrow = (w == 0) ? zbuf : errbuf[w - 1];
    float* __restrict__ myrow = errbuf[w];

    const int row = w * 32 + lane;
    const float* __restrict__ xrow = xp + (size_t)row * W;
    float* __restrict__ orow = op + (size_t)row * W;

    // Skew-2 delay line: at step t lane l consumes
    //   e_ur = r1 (row-above err at col c+1, shfl'd at end of step t-1)
    //   e_u  = r2 (col c,   shfl'd at t-2)
    //   e_ul = r3 (col c-1, shfl'd at t-3)
    // Lane 0 substitutes prevrow[t+2] into the shfl each step.
    float r1 = 0.0f, r2 = 0.0f, r3 = 0.0f;
    float left = 0.0f;

    int t = 0;
    for (int k = 0; k < NCHUNK; ++k) {
        if (w != 0) {
            unsigned need = (unsigned)(t + CH + LAG);
            if (need > NSTEP_PAD) need = NSTEP_PAD;
            while (progress[w - 1] < need) { /* spin */ }
        }
        __syncwarp();
        COMPILER_FENCE();   // acquire (compiler-level): no hoist above the poll

        if (k == 0 && lane == 0) {
            // e_ul(t=0) = prev[-1] = 0 (pad); e_u = prev[0]; e_ur = prev[1].
            r3 = 0.0f;
            r2 = prevrow[0];
            r1 = prevrow[1];
        }

        #pragma unroll
        for (int i = 0; i < CH; ++i, ++t) {
            const int c = t - SKEW * lane;
            const bool active = ((unsigned)c < (unsigned)W);
            const float e_ur = r1, e_u = r2, e_ul = r3;

            // Clamped-address load keeps inactive lanes branch-free (L1-hit).
            int cl = c < 0 ? 0 : (c > W - 1 ? W - 1 : c);
            float xv = __ldg(xrow + cl);

            // x = clip(x,-1,1); x01 = (x+1)/2  (exact, matches reference)
            xv = fminf(fmaxf(xv, -1.0f), 1.0f);
            float x01 = __fmul_rn(__fadd_rn(xv, 1.0f), 0.5f);

            // up = (1/16*e_ul + 5/16*e_u) + 3/16*e_ur  (reference order, no FMA)
            float u = __fadd_rn(__fadd_rn(__fmul_rn(0.0625f, e_ul),
                                          __fmul_rn(0.3125f, e_u)),
                                __fmul_rn(0.1875f, e_ur));
            float pre = __fadd_rn(x01, u);
            float raw = __fadd_rn(pre, __fmul_rn(0.4375f, left));
            float val = fminf(fmaxf(raw, 0.0f), 1.0f);

            // q = round-half-even(val), val in [0,1]  <=>  raw > 0.5.
            // d = 0.5 - raw has exact sign (Sterbenz in [0.25,1]); tie -> q=0.
            float d = __fadd_rn(0.5f, -raw);
            unsigned s = (unsigned)(__float_as_int(d) >> 31);
            // err = val - q exactly: val + (-1.0f masked); Sterbenz-exact.
            float err = __fadd_rn(val, __uint_as_float(s & 0xBF800000u));
            err = active ? err : 0.0f;   // inactive lanes feed zero padding

            if (active) {
                // output = 2*q - 1 in {-1,+1}
                orow[c] = __uint_as_float(0xBF800000u ^ (s & 0x80000000u));
                if (lane == 31) myrow[c] = err;   // hand off to next band
            }
            left = err;

            // Cross-lane propagation; lane 0 injects the prev band's err.
            float sh = __shfl_up_sync(0xFFFFFFFFu, err, 1);
            const int pi = t + SKEW;
            float pv = (pi < W) ? prevrow[pi] : 0.0f;  // broadcast LDS
            if (lane == 0) sh = pv;                    // SEL, no branch
            r3 = r2; r2 = r1; r1 = sh;
        }

        if (lane == 31) {
            COMPILER_FENCE();   // release (compiler-level): STS before counter
            progress[w] = (unsigned)t;   // volatile STS; in-order after myrow STS
        }
    }
}

extern "C" void kernel_launch(void* const* d_in, const int* in_sizes, int n_in,
                              void* d_out, int out_size) {
    (void)in_sizes; (void)n_in; (void)out_size;
    const float* x = (const float*)d_in[0];
    float* out = (float*)d_out;
    fs_dither_kernel<<<NPLANES, NWARPS * 32>>>(x, out);
}

// round 17
// speedup vs baseline: 1.1462x; 1.1267x over previous
#include <cuda_runtime.h>

#define W 512
#define H 512
#define NPLANES 96
#define SKEW 2               // lane l -> col c = t - 2l
#define NWARPS 16            // one band (32 rows) per warp
#define CH 16                // columns per sync chunk
#define LAG 64               // 32 rows * SKEW
#define NSTEP_PAD 576        // 512 + 2*31 = 574 -> 36 chunks of 16
#define NCHUNK (NSTEP_PAD / CH)
#define TP 17                // tile pitch (odd -> conflict-free per-step LDS)
#define TILE_WORDS (32 * TP) // 544 floats per warp tile

#define COMPILER_FENCE() asm volatile("" ::: "memory")

// Dynamic SMEM layout (floats):
//   errbuf[NWARPS][W] | zbuf[W] | intile[2][NWARPS][TILE_WORDS] | otile[NWARPS][TILE_WORDS]
#define SM_ERR 0
#define SM_Z   (NWARPS * W)
#define SM_IN  (SM_Z + W)
#define SM_OT  (SM_IN + 2 * NWARPS * TILE_WORDS)
#define SM_TOT (SM_OT + NWARPS * TILE_WORDS)
#define SMEM_BYTES (SM_TOT * 4)

// Cooperative, row-wise (coalesced) load of one chunk's input parallelogram:
// tile[r][m] = x[row r][tt - 2r + m] (clamped address, as the old per-step
// loads did). 2 rows per instruction: each row is a contiguous 64B segment
// (~5 sectors/instr) instead of 32 scattered sectors per per-step LDG.
__device__ __forceinline__ void coop_load(float* __restrict__ dst,
                                          const float* __restrict__ xwarp,
                                          int tt, int lane) {
    const int g = lane >> 4;         // 0/1: which row of the pair
    const int m = lane & 15;         // column within segment
    #pragma unroll
    for (int j = 0; j < 16; ++j) {
        const int r = 2 * j + g;
        int c = tt - 2 * r + m;
        int cl = c < 0 ? 0 : (c > W - 1 ? W - 1 : c);
        dst[r * TP + m] = __ldg(xwarp + r * W + cl);
    }
}

// Cooperative, row-wise (coalesced) flush of one chunk's outputs, predicated
// per element so edge columns are never written.
__device__ __forceinline__ void coop_flush(const float* __restrict__ src,
                                           float* __restrict__ owarp,
                                           int t0, int lane) {
    const int g = lane >> 4;
    const int m = lane & 15;
    #pragma unroll
    for (int j = 0; j < 16; ++j) {
        const int r = 2 * j + g;
        const int c = t0 - 2 * r + m;
        float v = src[r * TP + m];
        if ((unsigned)c < (unsigned)W) owarp[r * W + c] = v;
    }
}

// Floyd-Steinberg 1-bit error diffusion. Skew-2 wavefront engine, spin
// handoff and arithmetic identical to the 225us kernel; ONLY the global I/O
// is restructured: per-step scattered LDG/STG (32 L1tex wavefronts each,
// ~1024/chunk/warp — the measured ~3700-cyc chunk period matches L1tex
// wavefront saturation across ~5 active warps) are replaced by SMEM-staged
// tiles with coalesced cooperative load/flush (~250 wavefronts/chunk/warp).
__global__ void __launch_bounds__(NWARPS * 32, 1)
fs_dither_kernel(const float* __restrict__ x, float* __restrict__ out) {
    extern __shared__ float sm[];
    __shared__ volatile unsigned progress[NWARPS];

    const int tid = threadIdx.x;
    const int w = tid >> 5;
    const int lane = tid & 31;
    const int plane = blockIdx.x;

    const float* __restrict__ xp = x + (size_t)plane * (H * W);
    float* __restrict__ op = out + (size_t)plane * (H * W);

    float* errbuf = sm + SM_ERR;           // [NWARPS][W]
    float* zbuf = sm + SM_Z;               // [W]

    for (int i = tid; i < W; i += NWARPS * 32) zbuf[i] = 0.0f;
    if (tid < NWARPS) progress[tid] = 0u;
    __syncthreads();

    const float* __restrict__ prevrow = (w == 0) ? zbuf : (errbuf + (w - 1) * W);
    float* __restrict__ myrow = errbuf + w * W;

    const float* __restrict__ xwarp = xp + (size_t)(w * 32) * W;  // band rows
    float* __restrict__ owarp = op + (size_t)(w * 32) * W;
    float* __restrict__ it0 = sm + SM_IN + w * TILE_WORDS;                    // buf 0
    float* __restrict__ it1 = sm + SM_IN + NWARPS * TILE_WORDS + w * TILE_WORDS; // buf 1
    float* __restrict__ obuf = sm + SM_OT + w * TILE_WORDS;

    const bool is31 = (lane == 31);

    // Prime: chunk 0's input tile (independent of the band cascade).
    coop_load(it0, xwarp, 0, lane);

    // Skew-2 delay line: at step t lane l consumes
    //   e_ur = r1 (row-above err at col c+1), e_u = r2 (col c), e_ul = r3 (c-1).
    // Lane 0 substitutes prevrow[t+2] into the shfl each step.
    float r1 = 0.0f, r2 = 0.0f, r3 = 0.0f;
    float left = 0.0f;

    int t = 0;
    for (int k = 0; k < NCHUNK; ++k) {
        if (w != 0) {
            unsigned need = (unsigned)(t + CH + LAG);
            if (need > NSTEP_PAD) need = NSTEP_PAD;
            while (progress[w - 1] < need) { /* spin (proven fastest) */ }
        }
        __syncwarp();
        COMPILER_FENCE();   // acquire (compiler-level)

        if (k == 0 && lane == 0) {
            // e_ul(t=0) = prev[-1] = 0 (pad); e_u = prev[0]; e_ur = prev[1].
            r3 = 0.0f;
            r2 = prevrow[0];
            r1 = prevrow[1];
        }

        // Prefetch next chunk's tile (latency overlaps this chunk's compute).
        const float* ibuf = (k & 1) ? it1 : it0;
        if (k + 1 < NCHUNK)
            coop_load((k & 1) ? it0 : it1, xwarp, (k + 1) * CH, lane);
        __syncwarp();   // ibuf (written last iter / prime) visible cross-lane

        #pragma unroll
        for (int i = 0; i < CH; ++i, ++t) {
            const int c = t - SKEW * lane;
            const bool active = ((unsigned)c < (unsigned)W);
            const float e_ur = r1, e_u = r2, e_ul = r3;

            float xv = ibuf[lane * TP + i];   // conflict-free LDS (pitch 17)

            // x = clip(x,-1,1); x01 = (x+1)/2  (exact, matches reference)
            xv = fminf(fmaxf(xv, -1.0f), 1.0f);
            float x01 = __fmul_rn(__fadd_rn(xv, 1.0f), 0.5f);

            // up = (1/16*e_ul + 5/16*e_u) + 3/16*e_ur  (reference order, no FMA)
            float u = __fadd_rn(__fadd_rn(__fmul_rn(0.0625f, e_ul),
                                          __fmul_rn(0.3125f, e_u)),
                                __fmul_rn(0.1875f, e_ur));
            float pre = __fadd_rn(x01, u);
            float raw = __fadd_rn(pre, __fmul_rn(0.4375f, left));
            float val = fminf(fmaxf(raw, 0.0f), 1.0f);

            // q = round-half-even(val), val in [0,1]  <=>  raw > 0.5.
            // d = 0.5 - raw has exact sign (Sterbenz in [0.25,1]); tie -> q=0.
            float d = __fadd_rn(0.5f, -raw);
            unsigned s = (unsigned)(__float_as_int(d) >> 31);
            // err = val - q exactly: val + (-1.0f masked); Sterbenz-exact.
            float err = __fadd_rn(val, __uint_as_float(s & 0xBF800000u));
            err = active ? err : 0.0f;   // inactive lanes feed zero padding

            // Output to the SMEM tile (unconditional; garbage cols are never
            // flushed). output = 2*q - 1 in {-1,+1}.
            obuf[lane * TP + i] = __uint_as_float(0xBF800000u ^ (s & 0x80000000u));
            if (active & is31) myrow[c] = err;   // band handoff (as before)

            left = err;

            // Cross-lane propagation; lane 0 injects the prev band's err.
            float sh = __shfl_up_sync(0xFFFFFFFFu, err, 1);
            const int pi = t + SKEW;
            float pv = (pi < W) ? prevrow[pi] : 0.0f;  // broadcast LDS
            if (lane == 0) sh = pv;                    // SEL, no branch
            r3 = r2; r2 = r1; r1 = sh;
        }

        __syncwarp();                       // obuf visible cross-lane
        coop_flush(obuf, owarp, t - CH, lane);   // coalesced, predicated STG

        if (is31) {
            COMPILER_FENCE();               // release: STS before counter
            progress[w] = (unsigned)t;      // volatile STS, in-order after myrow
        }
    }
}

extern "C" void kernel_launch(void* const* d_in, const int* in_sizes, int n_in,
                              void* d_out, int out_size) {
    (void)in_sizes; (void)n_in; (void)out_size;
    const float* x = (const float*)d_in[0];
    float* out = (float*)d_out;
    cudaFuncSetAttribute(fs_dither_kernel,
                         cudaFuncAttributeMaxDynamicSharedMemorySize, SMEM_BYTES);
    fs_dither_kernel<<<NPLANES, NWARPS * 32, SMEM_BYTES>>>(x, out);
}